// round 2
// baseline (speedup 1.0000x reference)
#include <cuda_runtime.h>
#include <cuda_bf16.h>

// NCE loss (training branch, size_average=True), fused single kernel.
// N=4096, E=1024, V=50257, K=25. One CTA per row n; 13 warps, 2 dots each.
// Last CTA (threadfence + atomic ticket) performs the deterministic final sum.

#define MAX_N   4096
#define THREADS 416
#define NWARP   13
#define MAX_NK  32

__device__ float g_partials[MAX_N];
__device__ unsigned int g_count = 0;

__global__ __launch_bounds__(THREADS, 4)
void nce_fused(const float* __restrict__ x,
               const int*   __restrict__ target,
               const int*   __restrict__ noise_idx,
               const float* __restrict__ weight,
               const float* __restrict__ bias,
               const float* __restrict__ noise,
               float* __restrict__ out,
               int N, int E, int K)
{
    const int n    = blockIdx.x;
    const int tid  = threadIdx.x;
    const int lane = tid & 31;
    const int wid  = tid >> 5;
    const int nk   = K + 1;                // 26
    const float kf = (float)K;             // 25

    __shared__ float4 xs[256];             // x[n], E=1024 floats
    __shared__ int    sidx[MAX_NK];
    __shared__ float  sb[MAX_NK];          // bias[idx]
    __shared__ float  skn[MAX_NK];         // K * noise[idx]
    __shared__ float  wloss[NWARP];
    __shared__ float  red[THREADS];
    __shared__ bool   is_last;

    // Prefetch candidate indices + their bias/noise (decoupled from dot chain)
    if (tid < nk) {
        const int idx = (tid == 0) ? __ldg(&target[n])
                                   : __ldg(&noise_idx[n * K + (tid - 1)]);
        sidx[tid] = idx;
        sb[tid]   = __ldg(&bias[idx]);
        skn[tid]  = kf * __ldg(&noise[idx]);
    }

    // Stage x[n] into shared (coalesced float4)
    const float4* x4 = reinterpret_cast<const float4*>(x + (size_t)n * E);
    for (int i = tid; i < 256; i += THREADS) xs[i] = x4[i];
    __syncthreads();

    // Each warp handles k = wid and k = wid + 13  (26 = 2 * 13, perfectly balanced)
    float loss = 0.0f;
    for (int k = wid; k < nk; k += NWARP) {
        const int idx = sidx[k];
        const float4* wrow = reinterpret_cast<const float4*>(weight + (size_t)idx * E);

        float s = 0.0f;
        #pragma unroll
        for (int j = 0; j < 8; j++) {       // 8 independent LDG.128 per lane
            const float4 wv = __ldg(&wrow[lane + 32 * j]);
            const float4 xv = xs[lane + 32 * j];
            s += wv.x * xv.x + wv.y * xv.y + wv.z * xv.z + wv.w * xv.w;
        }
        #pragma unroll
        for (int o = 16; o; o >>= 1)
            s += __shfl_xor_sync(0xffffffffu, s, o);

        if (lane == 0) {
            const float p   = __expf(s + sb[k] - 9.0f);
            const float kpn = skn[k];
            const float num = (k == 0) ? p : kpn;
            loss += __logf(num / (p + kpn));
        }
    }

    if (lane == 0) wloss[wid] = loss;
    __syncthreads();

    if (tid == 0) {
        float t = 0.0f;
        #pragma unroll
        for (int w = 0; w < NWARP; w++) t += wloss[w];
        g_partials[n] = t;
        __threadfence();
        const unsigned int ticket = atomicAdd(&g_count, 1u);
        is_last = (ticket == (unsigned int)(gridDim.x - 1));
    }
    __syncthreads();

    // Last block: deterministic final reduction over all per-row partials
    if (is_last) {
        __threadfence();
        float s = 0.0f;
        for (int i = tid; i < N; i += THREADS) s += g_partials[i];
        red[tid] = s;
        __syncthreads();
        #pragma unroll
        for (int o = 256; o; o >>= 1) {
            if (tid < o && tid + o < THREADS) red[tid] += red[tid + o];
            __syncthreads();
        }
        if (tid == 0) {
            out[0] = -red[0] / (float)N;
            g_count = 0;                    // reset for next graph replay
        }
    }
}

extern "C" void kernel_launch(void* const* d_in, const int* in_sizes, int n_in,
                              void* d_out, int out_size)
{
    const float* x         = (const float*)d_in[0];
    const int*   target    = (const int*)  d_in[1];
    const int*   noise_idx = (const int*)  d_in[2];
    const float* weight    = (const float*)d_in[3];
    const float* bias      = (const float*)d_in[4];
    const float* noise     = (const float*)d_in[5];

    const int N = in_sizes[1];            // 4096
    const int E = in_sizes[0] / N;        // 1024
    const int K = in_sizes[2] / N;        // 25

    nce_fused<<<N, THREADS>>>(x, target, noise_idx, weight, bias, noise,
                              (float*)d_out, N, E, K);
}

// round 3
// speedup vs baseline: 1.0737x; 1.0737x over previous
#include <cuda_runtime.h>
#include <cuda_bf16.h>

// NCE loss (training branch, size_average=True), single fused kernel.
// N=4096, E=1024, V=50257, K=25.
// One CTA per row n: 256 threads / 8 warps, 32 regs -> 8 CTAs/SM = 64 warps/SM.
// Each warp does 3-4 of the 26 dot products (8 independent LDG.128 per lane).
// Last CTA (ticket) does the deterministic final sum.

#define MAX_N   4096
#define THREADS 256
#define NWARP   8
#define MAX_NK  32

__device__ float g_partials[MAX_N];
__device__ unsigned int g_count = 0;

__global__ __launch_bounds__(THREADS, 8)
void nce_fused(const float* __restrict__ x,
               const int*   __restrict__ target,
               const int*   __restrict__ noise_idx,
               const float* __restrict__ weight,
               const float* __restrict__ bias,
               const float* __restrict__ noise,
               float* __restrict__ out,
               int N, int E, int K)
{
    const int n    = blockIdx.x;
    const int tid  = threadIdx.x;
    const int lane = tid & 31;
    const int wid  = tid >> 5;
    const int nk   = K + 1;                // 26

    __shared__ float4 xs[256];             // x[n], E=1024 floats
    __shared__ int    sidx[MAX_NK];
    __shared__ float  sb[MAX_NK];          // bias[idx]
    __shared__ float  skn[MAX_NK];         // K * noise[idx]
    __shared__ float  wloss[NWARP];
    __shared__ float  red[THREADS];
    __shared__ bool   is_last;

    // Prefetch candidate indices + bias/noise (off the dot critical path)
    if (tid < nk) {
        const int idx = (tid == 0) ? __ldg(&target[n])
                                   : __ldg(&noise_idx[n * K + (tid - 1)]);
        sidx[tid] = idx;
        sb[tid]   = __ldg(&bias[idx]);
        skn[tid]  = (float)K * __ldg(&noise[idx]);
    }

    // Stage x[n] into shared (one coalesced float4 per thread)
    const float4* x4 = reinterpret_cast<const float4*>(x + (size_t)n * E);
    xs[tid] = x4[tid];
    __syncthreads();

    // Each warp owns k = wid, wid+8, wid+16, (wid+24)
    float loss = 0.0f;
    for (int k = wid; k < nk; k += NWARP) {
        const int idx = sidx[k];
        const float4* wrow = reinterpret_cast<const float4*>(weight + (size_t)idx * E);

        float s = 0.0f;
        #pragma unroll
        for (int j = 0; j < 8; j++) {       // 8 independent LDG.128 per lane
            const float4 wv = __ldg(&wrow[lane + 32 * j]);
            const float4 xv = xs[lane + 32 * j];
            s += wv.x * xv.x + wv.y * xv.y + wv.z * xv.z + wv.w * xv.w;
        }
        #pragma unroll
        for (int o = 16; o; o >>= 1)
            s += __shfl_xor_sync(0xffffffffu, s, o);

        if (lane == 0) {
            const float p   = __expf(s + sb[k] - 9.0f);
            const float kpn = skn[k];
            const float num = (k == 0) ? p : kpn;
            loss += __logf(num / (p + kpn));
        }
    }

    if (lane == 0) wloss[wid] = loss;
    __syncthreads();

    if (tid == 0) {
        float t = 0.0f;
        #pragma unroll
        for (int w = 0; w < NWARP; w++) t += wloss[w];
        g_partials[n] = t;
        __threadfence();
        const unsigned int ticket = atomicAdd(&g_count, 1u);
        is_last = (ticket == (unsigned int)(gridDim.x - 1));
    }
    __syncthreads();

    // Last CTA: deterministic final reduction over per-row partials
    if (is_last) {
        __threadfence();
        float s = 0.0f;
        for (int i = tid; i < N; i += THREADS) s += g_partials[i];
        red[tid] = s;
        __syncthreads();
        #pragma unroll
        for (int o = 128; o; o >>= 1) {
            if (tid < o) red[tid] += red[tid + o];
            __syncthreads();
        }
        if (tid == 0) {
            out[0] = -red[0] / (float)N;
            g_count = 0;                    // reset for next graph replay
        }
    }
}

extern "C" void kernel_launch(void* const* d_in, const int* in_sizes, int n_in,
                              void* d_out, int out_size)
{
    const float* x         = (const float*)d_in[0];
    const int*   target    = (const int*)  d_in[1];
    const int*   noise_idx = (const int*)  d_in[2];
    const float* weight    = (const float*)d_in[3];
    const float* bias      = (const float*)d_in[4];
    const float* noise     = (const float*)d_in[5];

    const int N = in_sizes[1];            // 4096
    const int E = in_sizes[0] / N;        // 1024
    const int K = in_sizes[2] / N;        // 25

    nce_fused<<<N, THREADS>>>(x, target, noise_idx, weight, bias, noise,
                              (float*)d_out, N, E, K);
}

// round 4
// speedup vs baseline: 1.1000x; 1.0245x over previous
#include <cuda_runtime.h>
#include <cuda_bf16.h>

// NCE loss (training branch, size_average=True), single fused kernel.
// N=4096, E=1024, V=50257, K=25.
// One CTA per row n: 256 threads / 8 warps, 32 regs -> 8 CTAs/SM.
// Fused final reduction via L2-only partials + acq_rel ticket atomic
// (NO __threadfence: gpu-scope fence emits CCTL.IVALL and flushes L1D,
//  which killed the gather's L1 reuse in the previous round).

#define MAX_N   4096
#define THREADS 256
#define NWARP   8
#define MAX_NK  32

__device__ float g_partials[MAX_N];
__device__ unsigned int g_count = 0;

__global__ __launch_bounds__(THREADS, 8)
void nce_fused(const float* __restrict__ x,
               const int*   __restrict__ target,
               const int*   __restrict__ noise_idx,
               const float* __restrict__ weight,
               const float* __restrict__ bias,
               const float* __restrict__ noise,
               float* __restrict__ out,
               int N, int E, int K)
{
    const int n    = blockIdx.x;
    const int tid  = threadIdx.x;
    const int lane = tid & 31;
    const int wid  = tid >> 5;
    const int nk   = K + 1;                // 26

    __shared__ float4 xs[256];             // x[n], E=1024 floats
    __shared__ int    sidx[MAX_NK];
    __shared__ float  sb[MAX_NK];          // bias[idx]
    __shared__ float  skn[MAX_NK];         // K * noise[idx]
    __shared__ float  wloss[NWARP];
    __shared__ float  red[THREADS];
    __shared__ bool   is_last;

    // Prefetch candidate indices + bias/noise (off the dot critical path)
    if (tid < nk) {
        const int idx = (tid == 0) ? __ldg(&target[n])
                                   : __ldg(&noise_idx[n * K + (tid - 1)]);
        sidx[tid] = idx;
        sb[tid]   = __ldg(&bias[idx]);
        skn[tid]  = (float)K * __ldg(&noise[idx]);
    }

    // Stage x[n] into shared (one coalesced float4 per thread)
    const float4* x4 = reinterpret_cast<const float4*>(x + (size_t)n * E);
    xs[tid] = x4[tid];
    __syncthreads();

    // Each warp owns k = wid, wid+8, wid+16, (wid+24)
    float loss = 0.0f;
    for (int k = wid; k < nk; k += NWARP) {
        const int idx = sidx[k];
        const float4* wrow = reinterpret_cast<const float4*>(weight + (size_t)idx * E);

        float s = 0.0f;
        #pragma unroll
        for (int j = 0; j < 8; j++) {       // 8 independent LDG.128 per lane
            const float4 wv = __ldg(&wrow[lane + 32 * j]);
            const float4 xv = xs[lane + 32 * j];
            s += wv.x * xv.x + wv.y * xv.y + wv.z * xv.z + wv.w * xv.w;
        }
        #pragma unroll
        for (int o = 16; o; o >>= 1)
            s += __shfl_xor_sync(0xffffffffu, s, o);

        if (lane == 0) {
            const float p   = __expf(s + sb[k] - 9.0f);
            const float kpn = skn[k];
            const float num = (k == 0) ? p : kpn;
            loss += __logf(num / (p + kpn));
        }
    }

    if (lane == 0) wloss[wid] = loss;
    __syncthreads();

    if (tid == 0) {
        float t = 0.0f;
        #pragma unroll
        for (int w = 0; w < NWARP; w++) t += wloss[w];
        // L2-only store: no L1 involvement, visible to the acq_rel ticket below.
        __stcg(&g_partials[n], t);
        unsigned int ticket;
        asm volatile("atom.acq_rel.gpu.global.add.u32 %0, [%1], %2;"
                     : "=r"(ticket)
                     : "l"(&g_count), "r"(1u)
                     : "memory");
        is_last = (ticket == (unsigned int)(gridDim.x - 1));
    }
    __syncthreads();

    // Last CTA: deterministic final reduction over per-row partials (L2 reads)
    if (is_last) {
        float s = 0.0f;
        for (int i = tid; i < N; i += THREADS) s += __ldcg(&g_partials[i]);
        red[tid] = s;
        __syncthreads();
        #pragma unroll
        for (int o = 128; o; o >>= 1) {
            if (tid < o) red[tid] += red[tid + o];
            __syncthreads();
        }
        if (tid == 0) {
            out[0] = -red[0] / (float)N;
            unsigned int zero = 0;          // reset ticket for next graph replay
            asm volatile("st.global.cg.u32 [%0], %1;" :: "l"(&g_count), "r"(zero) : "memory");
        }
    }
}

extern "C" void kernel_launch(void* const* d_in, const int* in_sizes, int n_in,
                              void* d_out, int out_size)
{
    const float* x         = (const float*)d_in[0];
    const int*   target    = (const int*)  d_in[1];
    const int*   noise_idx = (const int*)  d_in[2];
    const float* weight    = (const float*)d_in[3];
    const float* bias      = (const float*)d_in[4];
    const float* noise     = (const float*)d_in[5];

    const int N = in_sizes[1];            // 4096
    const int E = in_sizes[0] / N;        // 1024
    const int K = in_sizes[2] / N;        // 25

    nce_fused<<<N, THREADS>>>(x, target, noise_idx, weight, bias, noise,
                              (float*)d_out, N, E, K);
}

// round 5
// speedup vs baseline: 1.1765x; 1.0695x over previous
#include <cuda_runtime.h>
#include <cuda_bf16.h>

// NCE loss (training branch, size_average=True).
// N=4096, E=1024, V=50257, K=25.
// One CTA per row n: 256 threads / 8 warps, 32 regs -> 8 CTAs/SM.
// Epilogue: single float atomicAdd of -row_loss/N into out[0] (d_out zeroed
// by a memset node each replay). No partials array, no ticket, no 2nd kernel.

#define THREADS 256
#define NWARP   8

__global__ __launch_bounds__(THREADS, 8)
void nce_main(const float* __restrict__ x,
              const int*   __restrict__ target,
              const int*   __restrict__ noise_idx,
              const float* __restrict__ weight,
              const float* __restrict__ bias,
              const float* __restrict__ noise,
              float* __restrict__ out,
              int N, int E, int K)
{
    const int n    = blockIdx.x;
    const int tid  = threadIdx.x;
    const int lane = tid & 31;
    const int wid  = tid >> 5;
    const int nk   = K + 1;                // 26

    __shared__ float4 xs[256];             // x[n], E=1024 floats
    __shared__ float  wloss[NWARP];

    // Stage x[n] into shared (one coalesced float4 per thread)
    const float4* x4 = reinterpret_cast<const float4*>(x + (size_t)n * E);
    xs[tid] = x4[tid];
    __syncthreads();

    // Each warp owns k = wid, wid+8, wid+16, (wid+24)
    float loss = 0.0f;
    for (int k = wid; k < nk; k += NWARP) {
        const int idx = (k == 0) ? target[n] : noise_idx[n * K + (k - 1)];
        const float4* wrow = reinterpret_cast<const float4*>(weight + (size_t)idx * E);

        float s = 0.0f;
        #pragma unroll
        for (int j = 0; j < 8; j++) {       // 8 independent LDG.128 per lane
            const float4 wv = __ldg(&wrow[lane + 32 * j]);
            const float4 xv = xs[lane + 32 * j];
            s += wv.x * xv.x + wv.y * xv.y + wv.z * xv.z + wv.w * xv.w;
        }
        #pragma unroll
        for (int o = 16; o; o >>= 1)
            s += __shfl_xor_sync(0xffffffffu, s, o);

        if (lane == 0) {
            const float logit = s + __ldg(&bias[idx]);
            const float p     = __expf(logit - 9.0f);
            const float kpn   = 25.0f * __ldg(&noise[idx]);
            const float num   = (k == 0) ? p : kpn;
            loss += __logf(num / (p + kpn));
        }
    }

    if (lane == 0) wloss[wid] = loss;
    __syncthreads();

    if (tid == 0) {
        float t = 0.0f;
        #pragma unroll
        for (int w = 0; w < NWARP; w++) t += wloss[w];
        atomicAdd(out, -t / (float)N);     // one atomic per CTA, negligible contention
    }
}

extern "C" void kernel_launch(void* const* d_in, const int* in_sizes, int n_in,
                              void* d_out, int out_size)
{
    const float* x         = (const float*)d_in[0];
    const int*   target    = (const int*)  d_in[1];
    const int*   noise_idx = (const int*)  d_in[2];
    const float* weight    = (const float*)d_in[3];
    const float* bias      = (const float*)d_in[4];
    const float* noise     = (const float*)d_in[5];

    const int N = in_sizes[1];            // 4096
    const int E = in_sizes[0] / N;        // 1024
    const int K = in_sizes[2] / N;        // 25

    cudaMemsetAsync(d_out, 0, sizeof(float));   // zero accumulator each replay
    nce_main<<<N, THREADS>>>(x, target, noise_idx, weight, bias, noise,
                             (float*)d_out, N, E, K);
}